// round 1
// baseline (speedup 1.0000x reference)
#include <cuda_runtime.h>

// ============================================================================
// RetinaNet detection heads on GB300.
//
// For each pyramid level l (6 levels, W=H=64>>l), compute two 3x3 SAME convs
// (reg: 24 ch, cls: 54 ch) from 256 input channels, then scatter into the
// concatenated output layout:
//   bbox_delta[n][c][ off_l + a*HW + p ]   (c in [0,4), a in [0,6), o = c*6+a)
//   confs     [n][c][ off_l + a*HW + p ]   (c in [0,9), o = c*6+a)
// Output = flat concat of bbox_delta [16,4,32760] then confs [16,9,32760].
//
// Strategy: implicit GEMM per tile.
//   M = 64 flattened spatial positions (one image, one level)
//   N = 80 output channels (78 real: 0..23 reg, 24..77 cls; padded to 80)
//   K = 9 taps x 256 input channels, chunked TK=16 through shared memory.
// Weights+bias are repacked once per launch into [head][tap][ci][oc80] so the
// B-side smem fill is a straight linear copy (L2-resident, 1.44 MB).
// ============================================================================

#define TM 64
#define TN 80
#define TK 16
#define NTHREADS 256

#define C_IN 256
#define APW_TOTAL 32760              // sum over levels of A*H*W
#define REG_STRIDE_N (4 * APW_TOTAL) // 131040
#define CLS_STRIDE_N (9 * APW_TOTAL) // 294840
#define CONF_BASE (16 * 4 * APW_TOTAL) // 2096640

#define WPACK_ELEMS (2 * 9 * C_IN * TN)  // 368640

__device__ float g_wpack[WPACK_ELEMS];
__device__ float g_bias[2 * TN];

// ----------------------------------------------------------------------------
// Weight repack: [O,C,3,3] (reg||cls per head) -> [head][tap][ci][oc80]
// ----------------------------------------------------------------------------
__global__ void repack_kernel(const float* __restrict__ wr1, const float* __restrict__ br1,
                              const float* __restrict__ wc1, const float* __restrict__ bc1,
                              const float* __restrict__ wr2, const float* __restrict__ br2,
                              const float* __restrict__ wc2, const float* __restrict__ bc2)
{
    int idx = blockIdx.x * blockDim.x + threadIdx.x;
    if (idx < WPACK_ELEMS) {
        int n   = idx % TN;
        int ci  = (idx / TN) % C_IN;
        int tap = (idx / (TN * C_IN)) % 9;
        int hd  = idx / (TN * C_IN * 9);
        const float* wr = hd ? wr2 : wr1;
        const float* wc = hd ? wc2 : wc1;
        float v = 0.0f;
        if (n < 24)      v = wr[(n * C_IN + ci) * 9 + tap];
        else if (n < 78) v = wc[((n - 24) * C_IN + ci) * 9 + tap];
        g_wpack[idx] = v;
    }
    if (idx < 2 * TN) {
        int hd = idx / TN, n = idx % TN;
        const float* br = hd ? br2 : br1;
        const float* bc = hd ? bc2 : bc1;
        float v = 0.0f;
        if (n < 24)      v = br[n];
        else if (n < 78) v = bc[n - 24];
        g_bias[idx] = v;
    }
}

// ----------------------------------------------------------------------------
// Main head kernel.
// Grid: 1392 blocks.  Blocks per level: {1024, 256, 64, 16, 16, 16}
//   (= 16 images x ceil(HW/64) tiles).
// ----------------------------------------------------------------------------
__global__ __launch_bounds__(NTHREADS) void head_kernel(
    const float* __restrict__ f0, const float* __restrict__ f1,
    const float* __restrict__ f2, const float* __restrict__ f3,
    const float* __restrict__ f4, const float* __restrict__ f5,
    float* __restrict__ out)
{
    // ---- decode block -> (level, image, spatial tile) ----
    int b = blockIdx.x;
    int level, rem;
    if      (b < 1024) { level = 0; rem = b;        }
    else if (b < 1280) { level = 1; rem = b - 1024; }
    else if (b < 1344) { level = 2; rem = b - 1280; }
    else if (b < 1360) { level = 3; rem = b - 1344; }
    else if (b < 1376) { level = 4; rem = b - 1360; }
    else               { level = 5; rem = b - 1376; }

    int logT;                                  // log2(tiles per image)
    if      (level == 0) logT = 6;
    else if (level == 1) logT = 4;
    else if (level == 2) logT = 2;
    else                 logT = 0;
    int n_img = rem >> logT;
    int tile  = rem & ((1 << logT) - 1);

    const int logW = 6 - level;
    const int W    = 1 << logW;
    const int HW   = 1 << (2 * logW);
    const int p0   = tile * TM;
    const int head = (level < 2) ? 0 : 1;

    const float* X;
    switch (level) {
        case 0: X = f0; break;
        case 1: X = f1; break;
        case 2: X = f2; break;
        case 3: X = f3; break;
        case 4: X = f4; break;
        default: X = f5; break;
    }
    const float* Xn = X + (long)n_img * C_IN * HW;

    const int level_off[6] = {0, 24576, 30720, 32256, 32640, 32736};
    const int off = level_off[level];

    const float* Wp = g_wpack + head * (9 * C_IN * TN);

    // ---- thread mapping ----
    const int t  = threadIdx.x;
    const int tx = t & 15;     // output-channel group
    const int ty = t >> 4;     // spatial group: m = ty*4 + i

    // A-load mapping: thread loads (mA, kA + {0,4,8,12})
    const int mA = t & 63;
    const int kA = t >> 6;     // 0..3
    const int pA = p0 + mA;
    const bool pvalid = (pA < HW);
    const int h0 = pA >> logW;
    const int w0 = pA & (W - 1);

    __shared__ __align__(16) float As[TK][TM];
    __shared__ float Bs[TK * TN];

    float acc[4][5];
#pragma unroll
    for (int i = 0; i < 4; i++)
#pragma unroll
        for (int j = 0; j < 5; j++) acc[i][j] = 0.0f;

    // ---- main loop: taps outer, K-chunks inner ----
    for (int tap = 0; tap < 9; tap++) {
        const int dy = tap / 3 - 1;
        const int dx = tap % 3 - 1;
        const int hh = h0 + dy;
        const int ww = w0 + dx;
        const bool v = pvalid & ((unsigned)hh < (unsigned)W) & ((unsigned)ww < (unsigned)W);
        const float* aptr = Xn + (hh * W + ww);      // + ci*HW added per load
        const float* bptr = Wp + tap * (C_IN * TN);  // linear [ci][oc80]

        for (int kc = 0; kc < C_IN; kc += TK) {
            // load A chunk: As[k][m], k = kA + kk
#pragma unroll
            for (int kk = 0; kk < TK; kk += 4) {
                int ci = kc + kA + kk;
                As[kA + kk][mA] = v ? aptr[ci * HW] : 0.0f;
            }
            // load B chunk: linear copy (TK*TN = 1280 = 5*256)
#pragma unroll
            for (int r = 0; r < 5; r++) {
                Bs[t + r * NTHREADS] = bptr[kc * TN + t + r * NTHREADS];
            }
            __syncthreads();

#pragma unroll
            for (int k = 0; k < TK; k++) {
                float4 av = *reinterpret_cast<const float4*>(&As[k][ty << 2]);
                float a0 = av.x, a1 = av.y, a2 = av.z, a3 = av.w;
                float bb[5];
#pragma unroll
                for (int j = 0; j < 5; j++) bb[j] = Bs[k * TN + tx + 16 * j];
#pragma unroll
                for (int j = 0; j < 5; j++) {
                    acc[0][j] += a0 * bb[j];
                    acc[1][j] += a1 * bb[j];
                    acc[2][j] += a2 * bb[j];
                    acc[3][j] += a3 * bb[j];
                }
            }
            __syncthreads();
        }
    }

    // ---- epilogue: bias + scatter to concatenated layout ----
    const int p_base = p0 + (ty << 2);
#pragma unroll
    for (int j = 0; j < 5; j++) {
        int o = tx + 16 * j;
        if (o >= 78) continue;
        float bs = g_bias[head * TN + o];
        int cbase;
        if (o < 24) {
            int c = o / 6, a = o % 6;
            cbase = n_img * REG_STRIDE_N + c * APW_TOTAL + off + a * HW;
        } else {
            int oc = o - 24;
            int c = oc / 6, a = oc % 6;
            cbase = CONF_BASE + n_img * CLS_STRIDE_N + c * APW_TOTAL + off + a * HW;
        }
#pragma unroll
        for (int i = 0; i < 4; i++) {
            int p = p_base + i;
            if (p < HW) out[cbase + p] = acc[i][j] + bs;
        }
    }
}

// ----------------------------------------------------------------------------
extern "C" void kernel_launch(void* const* d_in, const int* in_sizes, int n_in,
                              void* d_out, int out_size)
{
    const float* f0 = (const float*)d_in[0];
    const float* f1 = (const float*)d_in[1];
    const float* f2 = (const float*)d_in[2];
    const float* f3 = (const float*)d_in[3];
    const float* f4 = (const float*)d_in[4];
    const float* f5 = (const float*)d_in[5];

    repack_kernel<<<(WPACK_ELEMS + NTHREADS - 1) / NTHREADS, NTHREADS>>>(
        (const float*)d_in[6],  (const float*)d_in[7],
        (const float*)d_in[8],  (const float*)d_in[9],
        (const float*)d_in[10], (const float*)d_in[11],
        (const float*)d_in[12], (const float*)d_in[13]);

    head_kernel<<<1392, NTHREADS>>>(f0, f1, f2, f3, f4, f5, (float*)d_out);
}

// round 5
// speedup vs baseline: 1.8971x; 1.8971x over previous
#include <cuda_runtime.h>
#include <cuda_fp16.h>
#include <cstdint>

// ============================================================================
// RetinaNet heads: fp16-split implicit GEMM via mma.sync (HMMA) on sm_103.
//
// D[128 pos x 80 ch] fp32 = sum over 9 taps x 256 in-ch of A*B, with
//   A*B ~= Ah*Bh + Al*Bh + Ah*Bl   (fp16 hi + fp16 residual; err ~2^-23)
// A tiles built on the fly from f32 features; B tiles pre-split + padded.
// ============================================================================

#define NTH 256
#define C_IN 256
#define APW_TOTAL 32760
#define REG_STRIDE_N (4 * APW_TOTAL)
#define CLS_STRIDE_N (9 * APW_TOTAL)
#define CONF_BASE (16 * 4 * APW_TOTAL)

#define LDK 72                       // smem row stride in halves (144 B)
#define A_SPLIT_B (128 * LDK * 2)    // 18432 B per A split
#define B_SPLIT_B (80 * LDK * 2)     // 11520 B per B split
#define B_OFF (2 * A_SPLIT_B)        // 36864
#define SMEM_TOTAL (2 * A_SPLIT_B + 2 * B_SPLIT_B)  // 59904

// B pack: [head 2][tap 9][kc 4][split 2][n 80][k 72] halves
#define BPACK_TILE (80 * LDK)                 // 5760 halves per split-tile
#define BPACK_ELEMS (2 * 9 * 4 * 2 * BPACK_TILE)
__device__ __align__(16) __half g_bpack[BPACK_ELEMS];
__device__ float g_bias[2 * 80];

// ---------------------------------------------------------------------------
__device__ __forceinline__ uint32_t smem_u32(const void* p) {
    uint32_t a;
    asm("{ .reg .u64 t; cvta.to.shared.u64 t, %1; cvt.u32.u64 %0, t; }" : "=r"(a) : "l"(p));
    return a;
}

__device__ __forceinline__ void ldsm_x4(uint32_t& r0, uint32_t& r1, uint32_t& r2, uint32_t& r3,
                                        uint32_t addr) {
    asm volatile("ldmatrix.sync.aligned.m8n8.x4.shared.b16 {%0,%1,%2,%3}, [%4];"
                 : "=r"(r0), "=r"(r1), "=r"(r2), "=r"(r3) : "r"(addr));
}
__device__ __forceinline__ void ldsm_x2(uint32_t& r0, uint32_t& r1, uint32_t addr) {
    asm volatile("ldmatrix.sync.aligned.m8n8.x2.shared.b16 {%0,%1}, [%2];"
                 : "=r"(r0), "=r"(r1) : "r"(addr));
}
__device__ __forceinline__ void mma_16816(float* d, const uint32_t* a, uint32_t b0, uint32_t b1) {
    asm volatile("mma.sync.aligned.m16n8k16.row.col.f32.f16.f16.f32 "
                 "{%0,%1,%2,%3}, {%4,%5,%6,%7}, {%8,%9}, {%0,%1,%2,%3};"
                 : "+f"(d[0]), "+f"(d[1]), "+f"(d[2]), "+f"(d[3])
                 : "r"(a[0]), "r"(a[1]), "r"(a[2]), "r"(a[3]), "r"(b0), "r"(b1));
}

// ---------------------------------------------------------------------------
// Repack: weights -> fp16 hi/lo, [head][tap][kc][split][n80][k72]; biases.
// ---------------------------------------------------------------------------
__global__ void repack_kernel(const float* __restrict__ wr1, const float* __restrict__ br1,
                              const float* __restrict__ wc1, const float* __restrict__ bc1,
                              const float* __restrict__ wr2, const float* __restrict__ br2,
                              const float* __restrict__ wc2, const float* __restrict__ bc2)
{
    int idx = blockIdx.x * blockDim.x + threadIdx.x;
    if (idx < BPACK_ELEMS) {
        int k     = idx % LDK;
        int n     = (idx / LDK) % 80;
        int split = (idx / (LDK * 80)) % 2;
        int kc    = (idx / (LDK * 80 * 2)) % 4;
        int tap   = (idx / (LDK * 80 * 2 * 4)) % 9;
        int head  = idx / (LDK * 80 * 2 * 4 * 9);
        float w = 0.0f;
        if (k < 64) {
            int ci = kc * 64 + k;
            const float* wr = head ? wr2 : wr1;
            const float* wc = head ? wc2 : wc1;
            if (n < 24)      w = wr[(n * C_IN + ci) * 9 + tap];
            else if (n < 78) w = wc[((n - 24) * C_IN + ci) * 9 + tap];
        }
        float hi = __half2float(__float2half_rn(w));
        g_bpack[idx] = __float2half_rn(split ? (w - hi) : hi);
    }
    if (idx < 160) {
        int head = idx / 80, o = idx % 80;
        const float* br = head ? br2 : br1;
        const float* bc = head ? bc2 : bc1;
        float v = 0.0f;
        if (o < 24)      v = br[o];
        else if (o < 78) v = bc[o - 24];
        g_bias[idx] = v;
    }
}

// ---------------------------------------------------------------------------
__device__ __forceinline__ void store_one(float* __restrict__ out, int o, float val,
                                          int n_img, int off_l, int HW, int p, int head)
{
    float bias = g_bias[head * 80 + o];
    int idx;
    if (o < 24) {
        int c = o / 6, a = o % 6;
        idx = n_img * REG_STRIDE_N + c * APW_TOTAL + off_l + a * HW + p;
    } else {
        int oc = o - 24;
        int c = oc / 6, a = oc % 6;
        idx = CONF_BASE + n_img * CLS_STRIDE_N + c * APW_TOTAL + off_l + a * HW + p;
    }
    out[idx] = val + bias;
}

// ---------------------------------------------------------------------------
// Main kernel: 720 CTAs x 256 threads. Tiles/level: {512,128,32,16,16,16}.
// ---------------------------------------------------------------------------
__global__ __launch_bounds__(NTH, 2) void head_kernel(
    const float* __restrict__ f0, const float* __restrict__ f1,
    const float* __restrict__ f2, const float* __restrict__ f3,
    const float* __restrict__ f4, const float* __restrict__ f5,
    float* __restrict__ out)
{
    extern __shared__ char smem_c[];
    const uint32_t sm = smem_u32(smem_c);
    const int t = threadIdx.x;
    const int wid = t >> 5;
    const int lane = t & 31;

    // ---- block -> (level, image, tile) ----
    int b = blockIdx.x;
    int level, rem;
    if      (b < 512) { level = 0; rem = b;       }
    else if (b < 640) { level = 1; rem = b - 512; }
    else if (b < 672) { level = 2; rem = b - 640; }
    else if (b < 688) { level = 3; rem = b - 672; }
    else if (b < 704) { level = 4; rem = b - 688; }
    else              { level = 5; rem = b - 704; }
    const int logT = (level == 0) ? 5 : (level == 1) ? 3 : (level == 2) ? 1 : 0;
    const int n_img = rem >> logT;
    const int tile  = rem & ((1 << logT) - 1);
    const int logW = 6 - level;
    const int W  = 1 << logW;
    const int HW = 1 << (2 * logW);
    const int p0 = tile << 7;
    const int head = (level < 2) ? 0 : 1;
    const float* X = (level == 0) ? f0 : (level == 1) ? f1 : (level == 2) ? f2
                   : (level == 3) ? f3 : (level == 4) ? f4 : f5;
    const float* Xn = X + (long)n_img * C_IN * HW;
    const int lvl_off[6] = {0, 24576, 30720, 32256, 32640, 32736};
    const int off_l = lvl_off[level];

    // ---- A-build mapping: thread -> (m row, half of the 64-ch chunk) ----
    const int m  = t & 127;
    const int kh = t >> 7;                 // 0/1 -> channels kh*32..kh*32+31
    const int pA = p0 + m;
    const bool pvalid = (pA < HW);
    const int h0 = pA >> logW;
    const int w0 = pA & (W - 1);

    // ---- MMA mapping: warp grid 4(M) x 2(N), warp tile m32 x n40 ----
    const int wm = (wid & 3) << 5;         // m0 of warp
    const int wn = (wid >> 2) * 40;        // n0 of warp
    const int arow = lane & 15, acol = lane >> 4;
    const int brow4 = (lane & 7) + ((lane >> 4) << 3), bcol4 = (lane >> 3) & 1;
    const int brow2 = (lane & 7), bcol2 = (lane >> 3) & 1;  // x2: lanes 0-15 used

    float acc[2][5][4];
#pragma unroll
    for (int i = 0; i < 2; i++)
#pragma unroll
        for (int j = 0; j < 5; j++)
#pragma unroll
            for (int r = 0; r < 4; r++) acc[i][j][r] = 0.0f;

    for (int s = 0; s < 36; ++s) {
        const int tap = s >> 2;
        const int kci = s & 3;

        // ---- B: linear copy of pre-split tiles (hi+lo = 23040 B) ----
        {
            const uint4* src = reinterpret_cast<const uint4*>(
                g_bpack + (size_t)(((head * 9 + tap) * 4 + kci) * 2) * BPACK_TILE);
            uint4* dst = reinterpret_cast<uint4*>(smem_c + B_OFF);
#pragma unroll
            for (int i = 0; i < 6; i++) {
                int idx = t + i * NTH;
                if (idx < 1440) dst[idx] = src[idx];
            }
        }

        // ---- A: f32 gmem -> fp16 hi/lo split -> smem [m][k] ----
        {
            const int dy = tap / 3 - 1;
            const int dx = tap % 3 - 1;
            const int hh = h0 + dy;
            const int ww = w0 + dx;
            const bool v = pvalid & ((unsigned)hh < (unsigned)W) & ((unsigned)ww < (unsigned)W);
            const float* aptr = Xn + (v ? (hh * W + ww) : 0) + (kci * 64 + kh * 32) * (long)HW;
#pragma unroll
            for (int g = 0; g < 2; g++) {
                float x[16];
#pragma unroll
                for (int j = 0; j < 16; j++)
                    x[j] = v ? __ldg(aptr + (g * 16 + j) * HW) : 0.0f;
                uint32_t hw_[8], lw_[8];
#pragma unroll
                for (int j = 0; j < 8; j++) {
                    __half2 h2 = __floats2half2_rn(x[2 * j], x[2 * j + 1]);
                    float r0 = x[2 * j]     - __half2float(__low2half(h2));
                    float r1 = x[2 * j + 1] - __half2float(__high2half(h2));
                    __half2 l2 = __floats2half2_rn(r0, r1);
                    hw_[j] = *reinterpret_cast<uint32_t*>(&h2);
                    lw_[j] = *reinterpret_cast<uint32_t*>(&l2);
                }
                const int koff = (kh * 32 + g * 16) * 2;   // bytes within row
                char* arow_p = smem_c + m * (LDK * 2) + koff;
                *reinterpret_cast<uint4*>(arow_p)      = make_uint4(hw_[0], hw_[1], hw_[2], hw_[3]);
                *reinterpret_cast<uint4*>(arow_p + 16) = make_uint4(hw_[4], hw_[5], hw_[6], hw_[7]);
                *reinterpret_cast<uint4*>(arow_p + A_SPLIT_B)      = make_uint4(lw_[0], lw_[1], lw_[2], lw_[3]);
                *reinterpret_cast<uint4*>(arow_p + A_SPLIT_B + 16) = make_uint4(lw_[4], lw_[5], lw_[6], lw_[7]);
            }
        }

        __syncthreads();

        // ---- MMA over 4 k16 steps: AhBh + AlBh + AhBl ----
#pragma unroll
        for (int ks = 0; ks < 4; ks++) {
            const int kb = ks * 32;   // byte offset of k-step within row

            uint32_t ah[2][4], al[2][4];
#pragma unroll
            for (int mi = 0; mi < 2; mi++) {
                uint32_t ad = sm + (wm + mi * 16 + arow) * (LDK * 2) + kb + acol * 16;
                ldsm_x4(ah[mi][0], ah[mi][1], ah[mi][2], ah[mi][3], ad);
                ldsm_x4(al[mi][0], al[mi][1], al[mi][2], al[mi][3], ad + A_SPLIT_B);
            }

            uint32_t bh[10];
            {
                uint32_t b0 = sm + B_OFF + kb;
                ldsm_x4(bh[0], bh[1], bh[2], bh[3], b0 + (wn + brow4) * (LDK * 2) + bcol4 * 16);
                ldsm_x4(bh[4], bh[5], bh[6], bh[7], b0 + (wn + 16 + brow4) * (LDK * 2) + bcol4 * 16);
                ldsm_x2(bh[8], bh[9],             b0 + (wn + 32 + brow2) * (LDK * 2) + bcol2 * 16);
            }
#pragma unroll
            for (int mi = 0; mi < 2; mi++)
#pragma unroll
                for (int nj = 0; nj < 5; nj++)
                    mma_16816(acc[mi][nj], ah[mi], bh[2 * nj], bh[2 * nj + 1]);
#pragma unroll
            for (int mi = 0; mi < 2; mi++)
#pragma unroll
                for (int nj = 0; nj < 5; nj++)
                    mma_16816(acc[mi][nj], al[mi], bh[2 * nj], bh[2 * nj + 1]);

            uint32_t bl[10];
            {
                uint32_t b0 = sm + B_OFF + B_SPLIT_B + kb;
                ldsm_x4(bl[0], bl[1], bl[2], bl[3], b0 + (wn + brow4) * (LDK * 2) + bcol4 * 16);
                ldsm_x4(bl[4], bl[5], bl[6], bl[7], b0 + (wn + 16 + brow4) * (LDK * 2) + bcol4 * 16);
                ldsm_x2(bl[8], bl[9],             b0 + (wn + 32 + brow2) * (LDK * 2) + bcol2 * 16);
            }
#pragma unroll
            for (int mi = 0; mi < 2; mi++)
#pragma unroll
                for (int nj = 0; nj < 5; nj++)
                    mma_16816(acc[mi][nj], ah[mi], bl[2 * nj], bl[2 * nj + 1]);
        }

        __syncthreads();
    }

    // ---- epilogue: bias + scatter ----
#pragma unroll
    for (int mi = 0; mi < 2; mi++) {
        const int prow = p0 + wm + mi * 16 + (lane >> 2);
#pragma unroll
        for (int nj = 0; nj < 5; nj++) {
            const int o0 = wn + nj * 8 + (lane & 3) * 2;
            if (prow < HW) {
                if (o0 < 78)     store_one(out, o0,     acc[mi][nj][0], n_img, off_l, HW, prow, head);
                if (o0 + 1 < 78) store_one(out, o0 + 1, acc[mi][nj][1], n_img, off_l, HW, prow, head);
            }
            if (prow + 8 < HW) {
                if (o0 < 78)     store_one(out, o0,     acc[mi][nj][2], n_img, off_l, HW, prow + 8, head);
                if (o0 + 1 < 78) store_one(out, o0 + 1, acc[mi][nj][3], n_img, off_l, HW, prow + 8, head);
            }
        }
    }
}

// ---------------------------------------------------------------------------
extern "C" void kernel_launch(void* const* d_in, const int* in_sizes, int n_in,
                              void* d_out, int out_size)
{
    cudaFuncSetAttribute(head_kernel, cudaFuncAttributeMaxDynamicSharedMemorySize, SMEM_TOTAL);

    repack_kernel<<<(BPACK_ELEMS + NTH - 1) / NTH, NTH>>>(
        (const float*)d_in[6],  (const float*)d_in[7],
        (const float*)d_in[8],  (const float*)d_in[9],
        (const float*)d_in[10], (const float*)d_in[11],
        (const float*)d_in[12], (const float*)d_in[13]);

    head_kernel<<<720, NTH, SMEM_TOTAL>>>(
        (const float*)d_in[0], (const float*)d_in[1], (const float*)d_in[2],
        (const float*)d_in[3], (const float*)d_in[4], (const float*)d_in[5],
        (float*)d_out);
}

// round 6
// speedup vs baseline: 2.7240x; 1.4359x over previous
#include <cuda_runtime.h>
#include <cuda_fp16.h>
#include <cstdint>

// ============================================================================
// RetinaNet heads: fp16-split implicit GEMM via mma.sync (HMMA) on sm_103.
// Round 6: software-pipelined stages (cp.async B double-buffer + register-
// staged A prefetch) and dense flattened-position grid (683 CTAs).
//
// D[128 pos x 80 ch] fp32 = sum over 9 taps x 256 in-ch of A*B, with
//   A*B ~= Ah*Bh + Al*Bh + Ah*Bl   (fp16 hi + fp16 residual)
// ============================================================================

#define NTH 256
#define C_IN 256
#define APW_TOTAL 32760
#define REG_STRIDE_N (4 * APW_TOTAL)
#define CLS_STRIDE_N (9 * APW_TOTAL)
#define CONF_BASE (16 * 4 * APW_TOTAL)

#define LDK 72                        // smem row stride in halves (144 B)
#define A_SPLIT_B (128 * LDK * 2)     // 18432 B per A split (hi / lo)
#define A_BYTES (2 * A_SPLIT_B)       // 36864
#define B_SPLIT_B (80 * LDK * 2)      // 11520 B per B split
#define B_STAGE_B (2 * B_SPLIT_B)     // 23040 (hi + lo contiguous)
#define B_OFF A_BYTES
#define SMEM_TOTAL (A_BYTES + 2 * B_STAGE_B)   // 82944

// B pack: [head 2][tap 9][kc 4][split 2][n 80][k 72] halves
#define BPACK_TILE (80 * LDK)
#define BPACK_ELEMS (2 * 9 * 4 * 2 * BPACK_TILE)
__device__ __align__(16) __half g_bpack[BPACK_ELEMS];
__device__ float g_bias[2 * 80];

// ---------------------------------------------------------------------------
__device__ __forceinline__ uint32_t smem_u32(const void* p) {
    uint32_t a;
    asm("{ .reg .u64 t; cvta.to.shared.u64 t, %1; cvt.u32.u64 %0, t; }" : "=r"(a) : "l"(p));
    return a;
}
__device__ __forceinline__ void cp_async16(uint32_t dst, const void* src) {
    asm volatile("cp.async.cg.shared.global [%0], [%1], 16;" :: "r"(dst), "l"(src));
}
#define CP_COMMIT() asm volatile("cp.async.commit_group;" ::: "memory")
#define CP_WAIT1()  asm volatile("cp.async.wait_group 1;" ::: "memory")

__device__ __forceinline__ void ldsm_x4(uint32_t& r0, uint32_t& r1, uint32_t& r2, uint32_t& r3,
                                        uint32_t addr) {
    asm volatile("ldmatrix.sync.aligned.m8n8.x4.shared.b16 {%0,%1,%2,%3}, [%4];"
                 : "=r"(r0), "=r"(r1), "=r"(r2), "=r"(r3) : "r"(addr));
}
__device__ __forceinline__ void ldsm_x2(uint32_t& r0, uint32_t& r1, uint32_t addr) {
    asm volatile("ldmatrix.sync.aligned.m8n8.x2.shared.b16 {%0,%1}, [%2];"
                 : "=r"(r0), "=r"(r1) : "r"(addr));
}
__device__ __forceinline__ void mma_16816(float* d, const uint32_t* a, uint32_t b0, uint32_t b1) {
    asm volatile("mma.sync.aligned.m16n8k16.row.col.f32.f16.f16.f32 "
                 "{%0,%1,%2,%3}, {%4,%5,%6,%7}, {%8,%9}, {%0,%1,%2,%3};"
                 : "+f"(d[0]), "+f"(d[1]), "+f"(d[2]), "+f"(d[3])
                 : "r"(a[0]), "r"(a[1]), "r"(a[2]), "r"(a[3]), "r"(b0), "r"(b1));
}

// ---------------------------------------------------------------------------
// Repack: weights -> fp16 hi/lo, [head][tap][kc][split][n80][k72]; biases.
// ---------------------------------------------------------------------------
__global__ void repack_kernel(const float* __restrict__ wr1, const float* __restrict__ br1,
                              const float* __restrict__ wc1, const float* __restrict__ bc1,
                              const float* __restrict__ wr2, const float* __restrict__ br2,
                              const float* __restrict__ wc2, const float* __restrict__ bc2)
{
    int idx = blockIdx.x * blockDim.x + threadIdx.x;
    if (idx < BPACK_ELEMS) {
        int k     = idx % LDK;
        int n     = (idx / LDK) % 80;
        int split = (idx / (LDK * 80)) % 2;
        int kc    = (idx / (LDK * 80 * 2)) % 4;
        int tap   = (idx / (LDK * 80 * 2 * 4)) % 9;
        int head  = idx / (LDK * 80 * 2 * 4 * 9);
        float w = 0.0f;
        if (k < 64) {
            int ci = kc * 64 + k;
            const float* wr = head ? wr2 : wr1;
            const float* wc = head ? wc2 : wc1;
            if (n < 24)      w = wr[(n * C_IN + ci) * 9 + tap];
            else if (n < 78) w = wc[((n - 24) * C_IN + ci) * 9 + tap];
        }
        float hi = __half2float(__float2half_rn(w));
        g_bpack[idx] = __float2half_rn(split ? (w - hi) : hi);
    }
    if (idx < 160) {
        int head = idx / 80, o = idx % 80;
        const float* br = head ? br2 : br1;
        const float* bc = head ? bc2 : bc1;
        float v = 0.0f;
        if (o < 24)      v = br[o];
        else if (o < 78) v = bc[o - 24];
        g_bias[idx] = v;
    }
}

// ---------------------------------------------------------------------------
__device__ __forceinline__ void store_one(float* __restrict__ out, int o, float val,
                                          int n_img, int off_l, int HW, int p, int head)
{
    float bias = g_bias[head * 80 + o];
    int idx;
    if (o < 24) {
        int c = o / 6, a = o % 6;
        idx = n_img * REG_STRIDE_N + c * APW_TOTAL + off_l + a * HW + p;
    } else {
        int oc = o - 24;
        int c = oc / 6, a = oc % 6;
        idx = CONF_BASE + n_img * CLS_STRIDE_N + c * APW_TOTAL + off_l + a * HW + p;
    }
    out[idx] = val + bias;
}

// ---------------------------------------------------------------------------
// Main kernel: 683 CTAs x 256 threads.
// CTAs per level (128 rows over flattened img*HW): {512,128,32,8,2,1}.
// ---------------------------------------------------------------------------
__global__ __launch_bounds__(NTH, 2) void head_kernel(
    const float* __restrict__ f0, const float* __restrict__ f1,
    const float* __restrict__ f2, const float* __restrict__ f3,
    const float* __restrict__ f4, const float* __restrict__ f5,
    float* __restrict__ out)
{
    extern __shared__ char smem_c[];
    const uint32_t sm = smem_u32(smem_c);
    const int t = threadIdx.x;
    const int wid = t >> 5;
    const int lane = t & 31;

    // ---- block -> (level, rem) over flattened img*HW rows ----
    int b = blockIdx.x;
    int level, rem;
    if      (b < 512) { level = 0; rem = b;       }
    else if (b < 640) { level = 1; rem = b - 512; }
    else if (b < 672) { level = 2; rem = b - 640; }
    else if (b < 680) { level = 3; rem = b - 672; }
    else if (b < 682) { level = 4; rem = b - 680; }
    else              { level = 5; rem = b - 682; }
    const int logW = 6 - level;
    const int W  = 1 << logW;
    const int HW = 1 << (2 * logW);
    const int head = (level < 2) ? 0 : 1;
    const float* X = (level == 0) ? f0 : (level == 1) ? f1 : (level == 2) ? f2
                   : (level == 3) ? f3 : (level == 4) ? f4 : f5;
    const int lvl_off[6] = {0, 24576, 30720, 32256, 32640, 32736};
    const int off_l = lvl_off[level];
    const int u0 = rem << 7;            // first flattened row of this CTA

    // ---- A-build mapping: thread -> (row m, half of the 64-ch chunk) ----
    const int m  = t & 127;
    const int kh = t >> 7;
    const int u  = u0 + m;
    const bool rv = (u < (HW << 4));    // 16 images
    const int img = rv ? (u >> (2 * logW)) : 0;
    const int pos = u & (HW - 1);
    const int h0 = pos >> logW;
    const int w0 = pos & (W - 1);
    const float* Xn = X + (long)img * C_IN * HW;

    // ---- MMA mapping: warp grid 4(M) x 2(N), warp tile m32 x n40 ----
    const int wm = (wid & 3) << 5;
    const int wn = (wid >> 2) * 40;
    const int arow = lane & 15, acol = lane >> 4;
    const int brow4 = (lane & 7) + ((lane >> 4) << 3), bcol4 = (lane >> 3) & 1;
    const int brow2 = (lane & 7), bcol2 = (lane >> 3) & 1;

    float acc[2][5][4];
#pragma unroll
    for (int i = 0; i < 2; i++)
#pragma unroll
        for (int j = 0; j < 5; j++)
#pragma unroll
            for (int r = 0; r < 4; r++) acc[i][j][r] = 0.0f;

    const char* bpack_base = (const char*)(g_bpack) +
        (size_t)(head * 9 * 4) * 2 * BPACK_TILE * sizeof(__half);

    // ---- prologue: B(0) cp.async, A(0) LDG into regs ----
    {
        const char* src = bpack_base;              // tap0, kc0
        uint32_t dst = sm + B_OFF;
#pragma unroll
        for (int i = 0; i < 6; i++) {
            int idx = t + i * NTH;
            if (idx < 1440) cp_async16(dst + idx * 16, src + idx * 16);
        }
        CP_COMMIT();
    }
    float xs[32];
    {
        // stage 0: tap=0 (dy=-1,dx=-1), kci=0
        const int hh = h0 - 1, ww = w0 - 1;
        const bool v = rv & ((unsigned)hh < (unsigned)W) & ((unsigned)ww < (unsigned)W);
        const float* aptr = Xn + (v ? (hh * W + ww) : 0) + (kh * 32) * (long)HW;
#pragma unroll
        for (int j = 0; j < 32; j++) xs[j] = v ? __ldg(aptr + j * HW) : 0.0f;
    }

    for (int s = 0; s < 36; ++s) {
        // ---- convert staged A(s) regs -> fp16 hi/lo words ----
        uint32_t hw_[16], lw_[16];
#pragma unroll
        for (int j = 0; j < 16; j++) {
            __half2 h2 = __floats2half2_rn(xs[2 * j], xs[2 * j + 1]);
            float r0 = xs[2 * j]     - __half2float(__low2half(h2));
            float r1 = xs[2 * j + 1] - __half2float(__high2half(h2));
            __half2 l2 = __floats2half2_rn(r0, r1);
            hw_[j] = *reinterpret_cast<uint32_t*>(&h2);
            lw_[j] = *reinterpret_cast<uint32_t*>(&l2);
        }

        __syncthreads();   // all warps done with A smem + B buf[(s-1)&1]

        // ---- issue B(s+1) into buf[(s+1)&1] ----
        if (s + 1 < 36) {
            const int sn = s + 1;
            const char* src = bpack_base +
                (size_t)(((sn >> 2) * 4 + (sn & 3)) * 2) * BPACK_TILE * sizeof(__half);
            uint32_t dst = sm + B_OFF + ((sn & 1) ? B_STAGE_B : 0);
#pragma unroll
            for (int i = 0; i < 6; i++) {
                int idx = t + i * NTH;
                if (idx < 1440) cp_async16(dst + idx * 16, src + idx * 16);
            }
        }
        CP_COMMIT();

        // ---- STS A(s) ----
        {
            char* arow_p = smem_c + m * (LDK * 2) + kh * 64;
            *reinterpret_cast<uint4*>(arow_p)      = make_uint4(hw_[0], hw_[1], hw_[2], hw_[3]);
            *reinterpret_cast<uint4*>(arow_p + 16) = make_uint4(hw_[4], hw_[5], hw_[6], hw_[7]);
            *reinterpret_cast<uint4*>(arow_p + 32) = make_uint4(hw_[8], hw_[9], hw_[10], hw_[11]);
            *reinterpret_cast<uint4*>(arow_p + 48) = make_uint4(hw_[12], hw_[13], hw_[14], hw_[15]);
            char* alow_p = arow_p + A_SPLIT_B;
            *reinterpret_cast<uint4*>(alow_p)      = make_uint4(lw_[0], lw_[1], lw_[2], lw_[3]);
            *reinterpret_cast<uint4*>(alow_p + 16) = make_uint4(lw_[4], lw_[5], lw_[6], lw_[7]);
            *reinterpret_cast<uint4*>(alow_p + 32) = make_uint4(lw_[8], lw_[9], lw_[10], lw_[11]);
            *reinterpret_cast<uint4*>(alow_p + 48) = make_uint4(lw_[12], lw_[13], lw_[14], lw_[15]);
        }

        CP_WAIT1();        // B(s) landed (B(s+1) may still fly)
        __syncthreads();   // A(s) + B(s) visible to all warps

        // ---- LDG A(s+1) into regs (lands during MMA below) ----
        if (s + 1 < 36) {
            const int sn = s + 1;
            const int tap = sn >> 2;
            const int dy = tap / 3 - 1, dx = tap % 3 - 1;
            const int hh = h0 + dy, ww = w0 + dx;
            const bool v = rv & ((unsigned)hh < (unsigned)W) & ((unsigned)ww < (unsigned)W);
            const float* aptr = Xn + (v ? (hh * W + ww) : 0) +
                                ((sn & 3) * 64 + kh * 32) * (long)HW;
#pragma unroll
            for (int j = 0; j < 32; j++) xs[j] = v ? __ldg(aptr + j * HW) : 0.0f;
        }

        // ---- MMA(s): 4 k16 steps x (AhBh + AlBh + AhBl) ----
        const uint32_t bbuf = sm + B_OFF + ((s & 1) ? B_STAGE_B : 0);
#pragma unroll
        for (int ks = 0; ks < 4; ks++) {
            const int kb = ks * 32;

            uint32_t ah[2][4], al[2][4];
#pragma unroll
            for (int mi = 0; mi < 2; mi++) {
                uint32_t ad = sm + (wm + mi * 16 + arow) * (LDK * 2) + kb + acol * 16;
                ldsm_x4(ah[mi][0], ah[mi][1], ah[mi][2], ah[mi][3], ad);
                ldsm_x4(al[mi][0], al[mi][1], al[mi][2], al[mi][3], ad + A_SPLIT_B);
            }

            uint32_t bh[10];
            {
                uint32_t b0 = bbuf + kb;
                ldsm_x4(bh[0], bh[1], bh[2], bh[3], b0 + (wn + brow4) * (LDK * 2) + bcol4 * 16);
                ldsm_x4(bh[4], bh[5], bh[6], bh[7], b0 + (wn + 16 + brow4) * (LDK * 2) + bcol4 * 16);
                ldsm_x2(bh[8], bh[9],             b0 + (wn + 32 + brow2) * (LDK * 2) + bcol2 * 16);
            }
#pragma unroll
            for (int mi = 0; mi < 2; mi++)
#pragma unroll
                for (int nj = 0; nj < 5; nj++)
                    mma_16816(acc[mi][nj], ah[mi], bh[2 * nj], bh[2 * nj + 1]);
#pragma unroll
            for (int mi = 0; mi < 2; mi++)
#pragma unroll
                for (int nj = 0; nj < 5; nj++)
                    mma_16816(acc[mi][nj], al[mi], bh[2 * nj], bh[2 * nj + 1]);

            uint32_t bl[10];
            {
                uint32_t b0 = bbuf + B_SPLIT_B + kb;
                ldsm_x4(bl[0], bl[1], bl[2], bl[3], b0 + (wn + brow4) * (LDK * 2) + bcol4 * 16);
                ldsm_x4(bl[4], bl[5], bl[6], bl[7], b0 + (wn + 16 + brow4) * (LDK * 2) + bcol4 * 16);
                ldsm_x2(bl[8], bl[9],             b0 + (wn + 32 + brow2) * (LDK * 2) + bcol2 * 16);
            }
#pragma unroll
            for (int mi = 0; mi < 2; mi++)
#pragma unroll
                for (int nj = 0; nj < 5; nj++)
                    mma_16816(acc[mi][nj], ah[mi], bl[2 * nj], bl[2 * nj + 1]);
        }
    }

    // ---- epilogue: bias + scatter (per-row img/pos from flattened index) ----
#pragma unroll
    for (int mi = 0; mi < 2; mi++) {
        const int ur0 = u0 + wm + mi * 16 + (lane >> 2);
#pragma unroll
        for (int half = 0; half < 2; half++) {
            const int ur = ur0 + half * 8;
            if (ur >= (HW << 4)) continue;
            const int img_e = ur >> (2 * logW);
            const int p_e   = ur & (HW - 1);
#pragma unroll
            for (int nj = 0; nj < 5; nj++) {
                const int o0 = wn + nj * 8 + (lane & 3) * 2;
                const float v0 = acc[mi][nj][half * 2];
                const float v1 = acc[mi][nj][half * 2 + 1];
                if (o0 < 78)     store_one(out, o0,     v0, img_e, off_l, HW, p_e, head);
                if (o0 + 1 < 78) store_one(out, o0 + 1, v1, img_e, off_l, HW, p_e, head);
            }
        }
    }
}

// ---------------------------------------------------------------------------
extern "C" void kernel_launch(void* const* d_in, const int* in_sizes, int n_in,
                              void* d_out, int out_size)
{
    cudaFuncSetAttribute(head_kernel, cudaFuncAttributeMaxDynamicSharedMemorySize, SMEM_TOTAL);

    repack_kernel<<<(BPACK_ELEMS + NTH - 1) / NTH, NTH>>>(
        (const float*)d_in[6],  (const float*)d_in[7],
        (const float*)d_in[8],  (const float*)d_in[9],
        (const float*)d_in[10], (const float*)d_in[11],
        (const float*)d_in[12], (const float*)d_in[13]);

    head_kernel<<<683, NTH, SMEM_TOTAL>>>(
        (const float*)d_in[0], (const float*)d_in[1], (const float*)d_in[2],
        (const float*)d_in[3], (const float*)d_in[4], (const float*)d_in[5],
        (float*)d_out);
}

// round 7
// speedup vs baseline: 2.9360x; 1.0778x over previous
#include <cuda_runtime.h>
#include <cuda_fp16.h>
#include <cstdint>

// ============================================================================
// RetinaNet heads: fp16-split implicit GEMM via mma.sync (HMMA) on sm_103.
// Round 7: one full barrier per stage; A smem hazard handled by warp-pair
// named barriers (A rows are pair-private); B cp.async double-buffer issued
// a full stage ahead; A-prefetch LDGs interleaved into the MMA k-loop.
//
// D[128 pos x 80 ch] fp32 = sum over 9 taps x 256 in-ch of A*B, with
//   A*B ~= Ah*Bh + Al*Bh + Ah*Bl   (fp16 hi + fp16 residual)
// ============================================================================

#define NTH 256
#define C_IN 256
#define APW_TOTAL 32760
#define REG_STRIDE_N (4 * APW_TOTAL)
#define CLS_STRIDE_N (9 * APW_TOTAL)
#define CONF_BASE (16 * 4 * APW_TOTAL)

#define LDK 72                        // smem row stride in halves (144 B)
#define A_SPLIT_B (128 * LDK * 2)     // 18432 B per A split (hi / lo)
#define A_BYTES (2 * A_SPLIT_B)       // 36864 (single A buffer)
#define B_SPLIT_B (80 * LDK * 2)      // 11520 B per B split
#define B_STAGE_B (2 * B_SPLIT_B)     // 23040 (hi + lo contiguous)
#define B_OFF A_BYTES
#define SMEM_TOTAL (A_BYTES + 2 * B_STAGE_B)   // 82944

// B pack: [head 2][stage 36][split 2][n 80][k 72] halves (stage = tap*4+kc)
#define BPACK_TILE (80 * LDK)
#define BPACK_ELEMS (2 * 9 * 4 * 2 * BPACK_TILE)
__device__ __align__(16) __half g_bpack[BPACK_ELEMS];
__device__ float g_bias[2 * 80];

// ---------------------------------------------------------------------------
__device__ __forceinline__ uint32_t smem_u32(const void* p) {
    uint32_t a;
    asm("{ .reg .u64 t; cvta.to.shared.u64 t, %1; cvt.u32.u64 %0, t; }" : "=r"(a) : "l"(p));
    return a;
}
__device__ __forceinline__ void cp_async16(uint32_t dst, const void* src) {
    asm volatile("cp.async.cg.shared.global [%0], [%1], 16;" :: "r"(dst), "l"(src));
}
#define CP_COMMIT() asm volatile("cp.async.commit_group;" ::: "memory")
#define CP_WAIT0()  asm volatile("cp.async.wait_group 0;" ::: "memory")
#define PAIR_BAR(id) asm volatile("bar.sync %0, 64;" :: "r"(id) : "memory")

__device__ __forceinline__ void ldsm_x4(uint32_t& r0, uint32_t& r1, uint32_t& r2, uint32_t& r3,
                                        uint32_t addr) {
    asm volatile("ldmatrix.sync.aligned.m8n8.x4.shared.b16 {%0,%1,%2,%3}, [%4];"
                 : "=r"(r0), "=r"(r1), "=r"(r2), "=r"(r3) : "r"(addr));
}
__device__ __forceinline__ void ldsm_x2(uint32_t& r0, uint32_t& r1, uint32_t addr) {
    asm volatile("ldmatrix.sync.aligned.m8n8.x2.shared.b16 {%0,%1}, [%2];"
                 : "=r"(r0), "=r"(r1) : "r"(addr));
}
__device__ __forceinline__ void mma_16816(float* d, const uint32_t* a, uint32_t b0, uint32_t b1) {
    asm volatile("mma.sync.aligned.m16n8k16.row.col.f32.f16.f16.f32 "
                 "{%0,%1,%2,%3}, {%4,%5,%6,%7}, {%8,%9}, {%0,%1,%2,%3};"
                 : "+f"(d[0]), "+f"(d[1]), "+f"(d[2]), "+f"(d[3])
                 : "r"(a[0]), "r"(a[1]), "r"(a[2]), "r"(a[3]), "r"(b0), "r"(b1));
}

// ---------------------------------------------------------------------------
// Repack: weights -> fp16 hi/lo, [head][stage][split][n80][k72]; biases.
// ---------------------------------------------------------------------------
__global__ void repack_kernel(const float* __restrict__ wr1, const float* __restrict__ br1,
                              const float* __restrict__ wc1, const float* __restrict__ bc1,
                              const float* __restrict__ wr2, const float* __restrict__ br2,
                              const float* __restrict__ wc2, const float* __restrict__ bc2)
{
    int idx = blockIdx.x * blockDim.x + threadIdx.x;
    if (idx < BPACK_ELEMS) {
        int k     = idx % LDK;
        int n     = (idx / LDK) % 80;
        int split = (idx / (LDK * 80)) % 2;
        int kc    = (idx / (LDK * 80 * 2)) % 4;
        int tap   = (idx / (LDK * 80 * 2 * 4)) % 9;
        int head  = idx / (LDK * 80 * 2 * 4 * 9);
        float w = 0.0f;
        if (k < 64) {
            int ci = kc * 64 + k;
            const float* wr = head ? wr2 : wr1;
            const float* wc = head ? wc2 : wc1;
            if (n < 24)      w = wr[(n * C_IN + ci) * 9 + tap];
            else if (n < 78) w = wc[((n - 24) * C_IN + ci) * 9 + tap];
        }
        float hi = __half2float(__float2half_rn(w));
        g_bpack[idx] = __float2half_rn(split ? (w - hi) : hi);
    }
    if (idx < 160) {
        int head = idx / 80, o = idx % 80;
        const float* br = head ? br2 : br1;
        const float* bc = head ? bc2 : bc1;
        float v = 0.0f;
        if (o < 24)      v = br[o];
        else if (o < 78) v = bc[o - 24];
        g_bias[idx] = v;
    }
}

// ---------------------------------------------------------------------------
__device__ __forceinline__ void store_one(float* __restrict__ out, int o, float val,
                                          int n_img, int off_l, int HW, int p, int head)
{
    float bias = g_bias[head * 80 + o];
    int idx;
    if (o < 24) {
        int c = o / 6, a = o % 6;
        idx = n_img * REG_STRIDE_N + c * APW_TOTAL + off_l + a * HW + p;
    } else {
        int oc = o - 24;
        int c = oc / 6, a = oc % 6;
        idx = CONF_BASE + n_img * CLS_STRIDE_N + c * APW_TOTAL + off_l + a * HW + p;
    }
    out[idx] = val + bias;
}

// ---------------------------------------------------------------------------
// Main kernel: 683 CTAs x 256 threads.
// CTAs per level (128 rows over flattened img*HW): {512,128,32,8,2,1}.
// ---------------------------------------------------------------------------
__global__ __launch_bounds__(NTH, 2) void head_kernel(
    const float* __restrict__ f0, const float* __restrict__ f1,
    const float* __restrict__ f2, const float* __restrict__ f3,
    const float* __restrict__ f4, const float* __restrict__ f5,
    float* __restrict__ out)
{
    extern __shared__ char smem_c[];
    const uint32_t sm = smem_u32(smem_c);
    const int t = threadIdx.x;
    const int wid = t >> 5;
    const int lane = t & 31;
    const int pair_id = (wid & 3) + 1;     // named barrier per warp pair {w, w+4}

    // ---- block -> (level, rem) over flattened img*HW rows ----
    int b = blockIdx.x;
    int level, rem;
    if      (b < 512) { level = 0; rem = b;       }
    else if (b < 640) { level = 1; rem = b - 512; }
    else if (b < 672) { level = 2; rem = b - 640; }
    else if (b < 680) { level = 3; rem = b - 672; }
    else if (b < 682) { level = 4; rem = b - 680; }
    else              { level = 5; rem = b - 682; }
    const int logW = 6 - level;
    const int W  = 1 << logW;
    const int HW = 1 << (2 * logW);
    const int head = (level < 2) ? 0 : 1;
    const float* X = (level == 0) ? f0 : (level == 1) ? f1 : (level == 2) ? f2
                   : (level == 3) ? f3 : (level == 4) ? f4 : f5;
    const int lvl_off[6] = {0, 24576, 30720, 32256, 32640, 32736};
    const int off_l = lvl_off[level];
    const int u0 = rem << 7;

    // ---- A-build mapping: thread -> (row m, half of the 64-ch chunk) ----
    const int m  = t & 127;
    const int kh = t >> 7;
    const int u  = u0 + m;
    const bool rv = (u < (HW << 4));
    const int img = rv ? (u >> (2 * logW)) : 0;
    const int pos = u & (HW - 1);
    const int h0 = pos >> logW;
    const int w0 = pos & (W - 1);
    const float* Xn = X + (long)img * C_IN * HW;

    // ---- MMA mapping: warp grid 4(M) x 2(N), warp tile m32 x n40 ----
    const int wm = (wid & 3) << 5;
    const int wn = (wid >> 2) * 40;
    const int arow = lane & 15, acol = lane >> 4;
    const int brow4 = (lane & 7) + ((lane >> 4) << 3), bcol4 = (lane >> 3) & 1;
    const int brow2 = (lane & 7), bcol2 = (lane >> 3) & 1;

    float acc[2][5][4];
#pragma unroll
    for (int i = 0; i < 2; i++)
#pragma unroll
        for (int j = 0; j < 5; j++)
#pragma unroll
            for (int r = 0; r < 4; r++) acc[i][j][r] = 0.0f;

    const char* bpack_base = (const char*)(g_bpack) +
        (size_t)(head * 36) * 2 * BPACK_TILE * sizeof(__half);

    float xs[32];

    // ---- prologue: B(0) cp.async; A(0) LDG+convert+STS; sync ----
    {
        uint32_t dst = sm + B_OFF;
#pragma unroll
        for (int i = 0; i < 6; i++) {
            int idx = t + i * NTH;
            if (idx < 1440) cp_async16(dst + idx * 16, bpack_base + idx * 16);
        }
        CP_COMMIT();

        const int hh = h0 - 1, ww = w0 - 1;   // tap 0: dy=-1, dx=-1; kc 0
        const bool v = rv & ((unsigned)hh < (unsigned)W) & ((unsigned)ww < (unsigned)W);
        const float* aptr = Xn + (v ? (hh * W + ww) : 0) + (kh * 32) * (long)HW;
#pragma unroll
        for (int j = 0; j < 32; j++) xs[j] = v ? __ldg(aptr + j * HW) : 0.0f;

        uint32_t hw_[16], lw_[16];
#pragma unroll
        for (int j = 0; j < 16; j++) {
            __half2 h2 = __floats2half2_rn(xs[2 * j], xs[2 * j + 1]);
            float r0 = xs[2 * j]     - __half2float(__low2half(h2));
            float r1 = xs[2 * j + 1] - __half2float(__high2half(h2));
            __half2 l2 = __floats2half2_rn(r0, r1);
            hw_[j] = *reinterpret_cast<uint32_t*>(&h2);
            lw_[j] = *reinterpret_cast<uint32_t*>(&l2);
        }
        char* arow_p = smem_c + m * (LDK * 2) + kh * 64;
        *reinterpret_cast<uint4*>(arow_p)      = make_uint4(hw_[0], hw_[1], hw_[2], hw_[3]);
        *reinterpret_cast<uint4*>(arow_p + 16) = make_uint4(hw_[4], hw_[5], hw_[6], hw_[7]);
        *reinterpret_cast<uint4*>(arow_p + 32) = make_uint4(hw_[8], hw_[9], hw_[10], hw_[11]);
        *reinterpret_cast<uint4*>(arow_p + 48) = make_uint4(hw_[12], hw_[13], hw_[14], hw_[15]);
        char* alow_p = arow_p + A_SPLIT_B;
        *reinterpret_cast<uint4*>(alow_p)      = make_uint4(lw_[0], lw_[1], lw_[2], lw_[3]);
        *reinterpret_cast<uint4*>(alow_p + 16) = make_uint4(lw_[4], lw_[5], lw_[6], lw_[7]);
        *reinterpret_cast<uint4*>(alow_p + 32) = make_uint4(lw_[8], lw_[9], lw_[10], lw_[11]);
        *reinterpret_cast<uint4*>(alow_p + 48) = make_uint4(lw_[12], lw_[13], lw_[14], lw_[15]);

        CP_WAIT0();
        __syncthreads();
    }

    for (int s = 0; s < 36; ++s) {
        const bool more = (s + 1 < 36);

        // ---- issue B(s+1) into buf[(s+1)&1] (freed by last stage's sync) ----
        if (more) {
            const char* src = bpack_base + (size_t)((s + 1) * 2) * BPACK_TILE * sizeof(__half);
            uint32_t dst = sm + B_OFF + (((s + 1) & 1) ? B_STAGE_B : 0);
#pragma unroll
            for (int i = 0; i < 6; i++) {
                int idx = t + i * NTH;
                if (idx < 1440) cp_async16(dst + idx * 16, src + idx * 16);
            }
            CP_COMMIT();
        }

        // ---- A(s+1) gmem address ----
        bool vN = false;
        const float* aptrN = Xn;
        if (more) {
            const int sn = s + 1;
            const int tap = sn >> 2;
            const int dy = tap / 3 - 1, dx = tap % 3 - 1;
            const int hh = h0 + dy, ww = w0 + dx;
            vN = rv & ((unsigned)hh < (unsigned)W) & ((unsigned)ww < (unsigned)W);
            aptrN = Xn + (vN ? (hh * W + ww) : 0) + ((sn & 3) * 64 + kh * 32) * (long)HW;
        }

        // ---- MMA(s): 4 k16 steps x (AhBh + AlBh + AhBl); LDGs at ks 0,1 ----
        const uint32_t bbuf = sm + B_OFF + ((s & 1) ? B_STAGE_B : 0);
#pragma unroll
        for (int ks = 0; ks < 4; ks++) {
            const int kb = ks * 32;

            if (ks == 0 && more) {
#pragma unroll
                for (int j = 0; j < 16; j++) xs[j] = vN ? __ldg(aptrN + j * HW) : 0.0f;
            }
            if (ks == 1 && more) {
#pragma unroll
                for (int j = 16; j < 32; j++) xs[j] = vN ? __ldg(aptrN + j * HW) : 0.0f;
            }

            uint32_t ah[2][4], al[2][4];
#pragma unroll
            for (int mi = 0; mi < 2; mi++) {
                uint32_t ad = sm + (wm + mi * 16 + arow) * (LDK * 2) + kb + acol * 16;
                ldsm_x4(ah[mi][0], ah[mi][1], ah[mi][2], ah[mi][3], ad);
                ldsm_x4(al[mi][0], al[mi][1], al[mi][2], al[mi][3], ad + A_SPLIT_B);
            }

            uint32_t bh[10];
            {
                uint32_t b0 = bbuf + kb;
                ldsm_x4(bh[0], bh[1], bh[2], bh[3], b0 + (wn + brow4) * (LDK * 2) + bcol4 * 16);
                ldsm_x4(bh[4], bh[5], bh[6], bh[7], b0 + (wn + 16 + brow4) * (LDK * 2) + bcol4 * 16);
                ldsm_x2(bh[8], bh[9],             b0 + (wn + 32 + brow2) * (LDK * 2) + bcol2 * 16);
            }
#pragma unroll
            for (int mi = 0; mi < 2; mi++)
#pragma unroll
                for (int nj = 0; nj < 5; nj++)
                    mma_16816(acc[mi][nj], ah[mi], bh[2 * nj], bh[2 * nj + 1]);
#pragma unroll
            for (int mi = 0; mi < 2; mi++)
#pragma unroll
                for (int nj = 0; nj < 5; nj++)
                    mma_16816(acc[mi][nj], al[mi], bh[2 * nj], bh[2 * nj + 1]);

            uint32_t bl[10];
            {
                uint32_t b0 = bbuf + B_SPLIT_B + kb;
                ldsm_x4(bl[0], bl[1], bl[2], bl[3], b0 + (wn + brow4) * (LDK * 2) + bcol4 * 16);
                ldsm_x4(bl[4], bl[5], bl[6], bl[7], b0 + (wn + 16 + brow4) * (LDK * 2) + bcol4 * 16);
                ldsm_x2(bl[8], bl[9],             b0 + (wn + 32 + brow2) * (LDK * 2) + bcol2 * 16);
            }
#pragma unroll
            for (int mi = 0; mi < 2; mi++)
#pragma unroll
                for (int nj = 0; nj < 5; nj++)
                    mma_16816(acc[mi][nj], ah[mi], bl[2 * nj], bl[2 * nj + 1]);
        }

        // ---- convert A(s+1), pair-barrier, STS into the single A buffer ----
        if (more) {
            uint32_t hw_[16], lw_[16];
#pragma unroll
            for (int j = 0; j < 16; j++) {
                __half2 h2 = __floats2half2_rn(xs[2 * j], xs[2 * j + 1]);
                float r0 = xs[2 * j]     - __half2float(__low2half(h2));
                float r1 = xs[2 * j + 1] - __half2float(__high2half(h2));
                __half2 l2 = __floats2half2_rn(r0, r1);
                hw_[j] = *reinterpret_cast<uint32_t*>(&h2);
                lw_[j] = *reinterpret_cast<uint32_t*>(&l2);
            }

            PAIR_BAR(pair_id);   // partner warp done reading A rows of this pair

            char* arow_p = smem_c + m * (LDK * 2) + kh * 64;
            *reinterpret_cast<uint4*>(arow_p)      = make_uint4(hw_[0], hw_[1], hw_[2], hw_[3]);
            *reinterpret_cast<uint4*>(arow_p + 16) = make_uint4(hw_[4], hw_[5], hw_[6], hw_[7]);
            *reinterpret_cast<uint4*>(arow_p + 32) = make_uint4(hw_[8], hw_[9], hw_[10], hw_[11]);
            *reinterpret_cast<uint4*>(arow_p + 48) = make_uint4(hw_[12], hw_[13], hw_[14], hw_[15]);
            char* alow_p = arow_p + A_SPLIT_B;
            *reinterpret_cast<uint4*>(alow_p)      = make_uint4(lw_[0], lw_[1], lw_[2], lw_[3]);
            *reinterpret_cast<uint4*>(alow_p + 16) = make_uint4(lw_[4], lw_[5], lw_[6], lw_[7]);
            *reinterpret_cast<uint4*>(alow_p + 32) = make_uint4(lw_[8], lw_[9], lw_[10], lw_[11]);
            *reinterpret_cast<uint4*>(alow_p + 48) = make_uint4(lw_[12], lw_[13], lw_[14], lw_[15]);
        }

        CP_WAIT0();        // B(s+1) landed (issued a full stage ago)
        __syncthreads();   // B buffer handoff + A visibility across pairs
    }

    // ---- epilogue: bias + scatter ----
#pragma unroll
    for (int mi = 0; mi < 2; mi++) {
        const int ur0 = u0 + wm + mi * 16 + (lane >> 2);
#pragma unroll
        for (int half = 0; half < 2; half++) {
            const int ur = ur0 + half * 8;
            if (ur >= (HW << 4)) continue;
            const int img_e = ur >> (2 * logW);
            const int p_e   = ur & (HW - 1);
#pragma unroll
            for (int nj = 0; nj < 5; nj++) {
                const int o0 = wn + nj * 8 + (lane & 3) * 2;
                const float v0 = acc[mi][nj][half * 2];
                const float v1 = acc[mi][nj][half * 2 + 1];
                if (o0 < 78)     store_one(out, o0,     v0, img_e, off_l, HW, p_e, head);
                if (o0 + 1 < 78) store_one(out, o0 + 1, v1, img_e, off_l, HW, p_e, head);
            }
        }
    }
}

// ---------------------------------------------------------------------------
extern "C" void kernel_launch(void* const* d_in, const int* in_sizes, int n_in,
                              void* d_out, int out_size)
{
    cudaFuncSetAttribute(head_kernel, cudaFuncAttributeMaxDynamicSharedMemorySize, SMEM_TOTAL);

    repack_kernel<<<(BPACK_ELEMS + NTH - 1) / NTH, NTH>>>(
        (const float*)d_in[6],  (const float*)d_in[7],
        (const float*)d_in[8],  (const float*)d_in[9],
        (const float*)d_in[10], (const float*)d_in[11],
        (const float*)d_in[12], (const float*)d_in[13]);

    head_kernel<<<683, NTH, SMEM_TOTAL>>>(
        (const float*)d_in[0], (const float*)d_in[1], (const float*)d_in[2],
        (const float*)d_in[3], (const float*)d_in[4], (const float*)d_in[5],
        (float*)d_out);
}

// round 8
// speedup vs baseline: 3.7294x; 1.2702x over previous
#include <cuda_runtime.h>
#include <cuda_fp16.h>
#include <cstdint>

// ============================================================================
// RetinaNet heads: fp16-split implicit GEMM via mma.sync (HMMA) on sm_103.
// Round 8: two-term split  A*B ~= Ah*Bh + Al*Bh  (B residual dropped; weights
// quantization error ~2^-12 relative, well under the 1e-3 threshold).
// Pipeline structure from round 7: one full barrier per stage, warp-pair
// named barriers for the A buffer, B cp.async double-buffer a stage ahead,
// A-prefetch LDGs interleaved into the MMA k-loop.
// ============================================================================

#define NTH 256
#define C_IN 256
#define APW_TOTAL 32760
#define REG_STRIDE_N (4 * APW_TOTAL)
#define CLS_STRIDE_N (9 * APW_TOTAL)
#define CONF_BASE (16 * 4 * APW_TOTAL)

#define LDK 72                        // smem row stride in halves (144 B)
#define A_SPLIT_B (128 * LDK * 2)     // 18432 B per A split (hi / lo)
#define A_BYTES (2 * A_SPLIT_B)       // 36864 (single A buffer)
#define B_STAGE_B (80 * LDK * 2)      // 11520 B per B stage (hi only)
#define B_OFF A_BYTES
#define SMEM_TOTAL (A_BYTES + 2 * B_STAGE_B)   // 59904

// B pack: [head 2][stage 36][n 80][k 72] halves (stage = tap*4+kc), hi only
#define BPACK_TILE (80 * LDK)
#define BPACK_ELEMS (2 * 36 * BPACK_TILE)
__device__ __align__(16) __half g_bpack[BPACK_ELEMS];
__device__ float g_bias[2 * 80];

// ---------------------------------------------------------------------------
__device__ __forceinline__ uint32_t smem_u32(const void* p) {
    uint32_t a;
    asm("{ .reg .u64 t; cvta.to.shared.u64 t, %1; cvt.u32.u64 %0, t; }" : "=r"(a) : "l"(p));
    return a;
}
__device__ __forceinline__ void cp_async16(uint32_t dst, const void* src) {
    asm volatile("cp.async.cg.shared.global [%0], [%1], 16;" :: "r"(dst), "l"(src));
}
#define CP_COMMIT() asm volatile("cp.async.commit_group;" ::: "memory")
#define CP_WAIT0()  asm volatile("cp.async.wait_group 0;" ::: "memory")
#define PAIR_BAR(id) asm volatile("bar.sync %0, 64;" :: "r"(id) : "memory")

__device__ __forceinline__ void ldsm_x4(uint32_t& r0, uint32_t& r1, uint32_t& r2, uint32_t& r3,
                                        uint32_t addr) {
    asm volatile("ldmatrix.sync.aligned.m8n8.x4.shared.b16 {%0,%1,%2,%3}, [%4];"
                 : "=r"(r0), "=r"(r1), "=r"(r2), "=r"(r3) : "r"(addr));
}
__device__ __forceinline__ void ldsm_x2(uint32_t& r0, uint32_t& r1, uint32_t addr) {
    asm volatile("ldmatrix.sync.aligned.m8n8.x2.shared.b16 {%0,%1}, [%2];"
                 : "=r"(r0), "=r"(r1) : "r"(addr));
}
__device__ __forceinline__ void mma_16816(float* d, const uint32_t* a, uint32_t b0, uint32_t b1) {
    asm volatile("mma.sync.aligned.m16n8k16.row.col.f32.f16.f16.f32 "
                 "{%0,%1,%2,%3}, {%4,%5,%6,%7}, {%8,%9}, {%0,%1,%2,%3};"
                 : "+f"(d[0]), "+f"(d[1]), "+f"(d[2]), "+f"(d[3])
                 : "r"(a[0]), "r"(a[1]), "r"(a[2]), "r"(a[3]), "r"(b0), "r"(b1));
}

// ---------------------------------------------------------------------------
// Repack: weights -> fp16 hi, [head][stage][n80][k72]; biases.
// ---------------------------------------------------------------------------
__global__ void repack_kernel(const float* __restrict__ wr1, const float* __restrict__ br1,
                              const float* __restrict__ wc1, const float* __restrict__ bc1,
                              const float* __restrict__ wr2, const float* __restrict__ br2,
                              const float* __restrict__ wc2, const float* __restrict__ bc2)
{
    int idx = blockIdx.x * blockDim.x + threadIdx.x;
    if (idx < BPACK_ELEMS) {
        int k     = idx % LDK;
        int n     = (idx / LDK) % 80;
        int stage = (idx / (LDK * 80)) % 36;
        int head  = idx / (LDK * 80 * 36);
        int kc  = stage & 3;
        int tap = stage >> 2;
        float w = 0.0f;
        if (k < 64) {
            int ci = kc * 64 + k;
            const float* wr = head ? wr2 : wr1;
            const float* wc = head ? wc2 : wc1;
            if (n < 24)      w = wr[(n * C_IN + ci) * 9 + tap];
            else if (n < 78) w = wc[((n - 24) * C_IN + ci) * 9 + tap];
        }
        g_bpack[idx] = __float2half_rn(w);
    }
    if (idx < 160) {
        int head = idx / 80, o = idx % 80;
        const float* br = head ? br2 : br1;
        const float* bc = head ? bc2 : bc1;
        float v = 0.0f;
        if (o < 24)      v = br[o];
        else if (o < 78) v = bc[o - 24];
        g_bias[idx] = v;
    }
}

// ---------------------------------------------------------------------------
__device__ __forceinline__ void store_one(float* __restrict__ out, int o, float val,
                                          int n_img, int off_l, int HW, int p, int head)
{
    float bias = g_bias[head * 80 + o];
    int idx;
    if (o < 24) {
        int c = o / 6, a = o % 6;
        idx = n_img * REG_STRIDE_N + c * APW_TOTAL + off_l + a * HW + p;
    } else {
        int oc = o - 24;
        int c = oc / 6, a = oc % 6;
        idx = CONF_BASE + n_img * CLS_STRIDE_N + c * APW_TOTAL + off_l + a * HW + p;
    }
    out[idx] = val + bias;
}

// ---------------------------------------------------------------------------
// Main kernel: 683 CTAs x 256 threads.
// CTAs per level (128 rows over flattened img*HW): {512,128,32,8,2,1}.
// ---------------------------------------------------------------------------
__global__ __launch_bounds__(NTH, 2) void head_kernel(
    const float* __restrict__ f0, const float* __restrict__ f1,
    const float* __restrict__ f2, const float* __restrict__ f3,
    const float* __restrict__ f4, const float* __restrict__ f5,
    float* __restrict__ out)
{
    extern __shared__ char smem_c[];
    const uint32_t sm = smem_u32(smem_c);
    const int t = threadIdx.x;
    const int wid = t >> 5;
    const int lane = t & 31;
    const int pair_id = (wid & 3) + 1;     // named barrier per warp pair {w, w+4}

    // ---- block -> (level, rem) over flattened img*HW rows ----
    int b = blockIdx.x;
    int level, rem;
    if      (b < 512) { level = 0; rem = b;       }
    else if (b < 640) { level = 1; rem = b - 512; }
    else if (b < 672) { level = 2; rem = b - 640; }
    else if (b < 680) { level = 3; rem = b - 672; }
    else if (b < 682) { level = 4; rem = b - 680; }
    else              { level = 5; rem = b - 682; }
    const int logW = 6 - level;
    const int W  = 1 << logW;
    const int HW = 1 << (2 * logW);
    const int head = (level < 2) ? 0 : 1;
    const float* X = (level == 0) ? f0 : (level == 1) ? f1 : (level == 2) ? f2
                   : (level == 3) ? f3 : (level == 4) ? f4 : f5;
    const int lvl_off[6] = {0, 24576, 30720, 32256, 32640, 32736};
    const int off_l = lvl_off[level];
    const int u0 = rem << 7;

    // ---- A-build mapping: thread -> (row m, half of the 64-ch chunk) ----
    const int m  = t & 127;
    const int kh = t >> 7;
    const int u  = u0 + m;
    const bool rv = (u < (HW << 4));
    const int img = rv ? (u >> (2 * logW)) : 0;
    const int pos = u & (HW - 1);
    const int h0 = pos >> logW;
    const int w0 = pos & (W - 1);
    const float* Xn = X + (long)img * C_IN * HW;

    // ---- MMA mapping: warp grid 4(M) x 2(N), warp tile m32 x n40 ----
    const int wm = (wid & 3) << 5;
    const int wn = (wid >> 2) * 40;
    const int arow = lane & 15, acol = lane >> 4;
    const int brow4 = (lane & 7) + ((lane >> 4) << 3), bcol4 = (lane >> 3) & 1;
    const int brow2 = (lane & 7), bcol2 = (lane >> 3) & 1;

    float acc[2][5][4];
#pragma unroll
    for (int i = 0; i < 2; i++)
#pragma unroll
        for (int j = 0; j < 5; j++)
#pragma unroll
            for (int r = 0; r < 4; r++) acc[i][j][r] = 0.0f;

    const char* bpack_base = (const char*)(g_bpack) +
        (size_t)(head * 36) * BPACK_TILE * sizeof(__half);

    float xs[32];

    // ---- prologue: B(0) cp.async; A(0) LDG+convert+STS; sync ----
    {
        uint32_t dst = sm + B_OFF;
#pragma unroll
        for (int i = 0; i < 3; i++) {
            int idx = t + i * NTH;
            if (idx < 720) cp_async16(dst + idx * 16, bpack_base + idx * 16);
        }
        CP_COMMIT();

        const int hh = h0 - 1, ww = w0 - 1;   // tap 0: dy=-1, dx=-1; kc 0
        const bool v = rv & ((unsigned)hh < (unsigned)W) & ((unsigned)ww < (unsigned)W);
        const float* aptr = Xn + (v ? (hh * W + ww) : 0) + (kh * 32) * (long)HW;
#pragma unroll
        for (int j = 0; j < 32; j++) xs[j] = v ? __ldg(aptr + j * HW) : 0.0f;

        uint32_t hw_[16], lw_[16];
#pragma unroll
        for (int j = 0; j < 16; j++) {
            __half2 h2 = __floats2half2_rn(xs[2 * j], xs[2 * j + 1]);
            float r0 = xs[2 * j]     - __half2float(__low2half(h2));
            float r1 = xs[2 * j + 1] - __half2float(__high2half(h2));
            __half2 l2 = __floats2half2_rn(r0, r1);
            hw_[j] = *reinterpret_cast<uint32_t*>(&h2);
            lw_[j] = *reinterpret_cast<uint32_t*>(&l2);
        }
        char* arow_p = smem_c + m * (LDK * 2) + kh * 64;
        *reinterpret_cast<uint4*>(arow_p)      = make_uint4(hw_[0], hw_[1], hw_[2], hw_[3]);
        *reinterpret_cast<uint4*>(arow_p + 16) = make_uint4(hw_[4], hw_[5], hw_[6], hw_[7]);
        *reinterpret_cast<uint4*>(arow_p + 32) = make_uint4(hw_[8], hw_[9], hw_[10], hw_[11]);
        *reinterpret_cast<uint4*>(arow_p + 48) = make_uint4(hw_[12], hw_[13], hw_[14], hw_[15]);
        char* alow_p = arow_p + A_SPLIT_B;
        *reinterpret_cast<uint4*>(alow_p)      = make_uint4(lw_[0], lw_[1], lw_[2], lw_[3]);
        *reinterpret_cast<uint4*>(alow_p + 16) = make_uint4(lw_[4], lw_[5], lw_[6], lw_[7]);
        *reinterpret_cast<uint4*>(alow_p + 32) = make_uint4(lw_[8], lw_[9], lw_[10], lw_[11]);
        *reinterpret_cast<uint4*>(alow_p + 48) = make_uint4(lw_[12], lw_[13], lw_[14], lw_[15]);

        CP_WAIT0();
        __syncthreads();
    }

    for (int s = 0; s < 36; ++s) {
        const bool more = (s + 1 < 36);

        // ---- issue B(s+1) into buf[(s+1)&1] (freed by last stage's sync) ----
        if (more) {
            const char* src = bpack_base + (size_t)(s + 1) * BPACK_TILE * sizeof(__half);
            uint32_t dst = sm + B_OFF + (((s + 1) & 1) ? B_STAGE_B : 0);
#pragma unroll
            for (int i = 0; i < 3; i++) {
                int idx = t + i * NTH;
                if (idx < 720) cp_async16(dst + idx * 16, src + idx * 16);
            }
            CP_COMMIT();
        }

        // ---- A(s+1) gmem address ----
        bool vN = false;
        const float* aptrN = Xn;
        if (more) {
            const int sn = s + 1;
            const int tap = sn >> 2;
            const int dy = tap / 3 - 1, dx = tap % 3 - 1;
            const int hh = h0 + dy, ww = w0 + dx;
            vN = rv & ((unsigned)hh < (unsigned)W) & ((unsigned)ww < (unsigned)W);
            aptrN = Xn + (vN ? (hh * W + ww) : 0) + ((sn & 3) * 64 + kh * 32) * (long)HW;
        }

        // ---- MMA(s): 4 k16 steps x (AhBh + AlBh); LDGs at ks 0,1 ----
        const uint32_t bbuf = sm + B_OFF + ((s & 1) ? B_STAGE_B : 0);
#pragma unroll
        for (int ks = 0; ks < 4; ks++) {
            const int kb = ks * 32;

            if (ks == 0 && more) {
#pragma unroll
                for (int j = 0; j < 16; j++) xs[j] = vN ? __ldg(aptrN + j * HW) : 0.0f;
            }
            if (ks == 1 && more) {
#pragma unroll
                for (int j = 16; j < 32; j++) xs[j] = vN ? __ldg(aptrN + j * HW) : 0.0f;
            }

            uint32_t ah[2][4], al[2][4];
#pragma unroll
            for (int mi = 0; mi < 2; mi++) {
                uint32_t ad = sm + (wm + mi * 16 + arow) * (LDK * 2) + kb + acol * 16;
                ldsm_x4(ah[mi][0], ah[mi][1], ah[mi][2], ah[mi][3], ad);
                ldsm_x4(al[mi][0], al[mi][1], al[mi][2], al[mi][3], ad + A_SPLIT_B);
            }

            uint32_t bh[10];
            {
                uint32_t b0 = bbuf + kb;
                ldsm_x4(bh[0], bh[1], bh[2], bh[3], b0 + (wn + brow4) * (LDK * 2) + bcol4 * 16);
                ldsm_x4(bh[4], bh[5], bh[6], bh[7], b0 + (wn + 16 + brow4) * (LDK * 2) + bcol4 * 16);
                ldsm_x2(bh[8], bh[9],             b0 + (wn + 32 + brow2) * (LDK * 2) + bcol2 * 16);
            }
#pragma unroll
            for (int mi = 0; mi < 2; mi++)
#pragma unroll
                for (int nj = 0; nj < 5; nj++)
                    mma_16816(acc[mi][nj], ah[mi], bh[2 * nj], bh[2 * nj + 1]);
#pragma unroll
            for (int mi = 0; mi < 2; mi++)
#pragma unroll
                for (int nj = 0; nj < 5; nj++)
                    mma_16816(acc[mi][nj], al[mi], bh[2 * nj], bh[2 * nj + 1]);
        }

        // ---- convert A(s+1), pair-barrier, STS into the single A buffer ----
        if (more) {
            uint32_t hw_[16], lw_[16];
#pragma unroll
            for (int j = 0; j < 16; j++) {
                __half2 h2 = __floats2half2_rn(xs[2 * j], xs[2 * j + 1]);
                float r0 = xs[2 * j]     - __half2float(__low2half(h2));
                float r1 = xs[2 * j + 1] - __half2float(__high2half(h2));
                __half2 l2 = __floats2half2_rn(r0, r1);
                hw_[j] = *reinterpret_cast<uint32_t*>(&h2);
                lw_[j] = *reinterpret_cast<uint32_t*>(&l2);
            }

            PAIR_BAR(pair_id);   // partner warp done reading A rows of this pair

            char* arow_p = smem_c + m * (LDK * 2) + kh * 64;
            *reinterpret_cast<uint4*>(arow_p)      = make_uint4(hw_[0], hw_[1], hw_[2], hw_[3]);
            *reinterpret_cast<uint4*>(arow_p + 16) = make_uint4(hw_[4], hw_[5], hw_[6], hw_[7]);
            *reinterpret_cast<uint4*>(arow_p + 32) = make_uint4(hw_[8], hw_[9], hw_[10], hw_[11]);
            *reinterpret_cast<uint4*>(arow_p + 48) = make_uint4(hw_[12], hw_[13], hw_[14], hw_[15]);
            char* alow_p = arow_p + A_SPLIT_B;
            *reinterpret_cast<uint4*>(alow_p)      = make_uint4(lw_[0], lw_[1], lw_[2], lw_[3]);
            *reinterpret_cast<uint4*>(alow_p + 16) = make_uint4(lw_[4], lw_[5], lw_[6], lw_[7]);
            *reinterpret_cast<uint4*>(alow_p + 32) = make_uint4(lw_[8], lw_[9], lw_[10], lw_[11]);
            *reinterpret_cast<uint4*>(alow_p + 48) = make_uint4(lw_[12], lw_[13], lw_[14], lw_[15]);
        }

        CP_WAIT0();        // B(s+1) landed (issued a full stage ago)
        __syncthreads();   // B buffer handoff + A visibility across pairs
    }

    // ---- epilogue: bias + scatter ----
#pragma unroll
    for (int mi = 0; mi < 2; mi++) {
        const int ur0 = u0 + wm + mi * 16 + (lane >> 2);
#pragma unroll
        for (int half = 0; half < 2; half++) {
            const int ur = ur0 + half * 8;
            if (ur >= (HW << 4)) continue;
            const int img_e = ur >> (2 * logW);
            const int p_e   = ur & (HW - 1);
#pragma unroll
            for (int nj = 0; nj < 5; nj++) {
                const int o0 = wn + nj * 8 + (lane & 3) * 2;
                const float v0 = acc[mi][nj][half * 2];
                const float v1 = acc[mi][nj][half * 2 + 1];
                if (o0 < 78)     store_one(out, o0,     v0, img_e, off_l, HW, p_e, head);
                if (o0 + 1 < 78) store_one(out, o0 + 1, v1, img_e, off_l, HW, p_e, head);
            }
        }
    }
}

// ---------------------------------------------------------------------------
extern "C" void kernel_launch(void* const* d_in, const int* in_sizes, int n_in,
                              void* d_out, int out_size)
{
    cudaFuncSetAttribute(head_kernel, cudaFuncAttributeMaxDynamicSharedMemorySize, SMEM_TOTAL);

    repack_kernel<<<(BPACK_ELEMS + NTH - 1) / NTH, NTH>>>(
        (const float*)d_in[6],  (const float*)d_in[7],
        (const float*)d_in[8],  (const float*)d_in[9],
        (const float*)d_in[10], (const float*)d_in[11],
        (const float*)d_in[12], (const float*)d_in[13]);

    head_kernel<<<683, NTH, SMEM_TOTAL>>>(
        (const float*)d_in[0], (const float*)d_in[1], (const float*)d_in[2],
        (const float*)d_in[3], (const float*)d_in[4], (const float*)d_in[5],
        (float*)d_out);
}

// round 9
// speedup vs baseline: 5.3103x; 1.4239x over previous
#include <cuda_runtime.h>
#include <cuda_fp16.h>
#include <cstdint>

// ============================================================================
// RetinaNet heads: pure fp16 implicit GEMM via mma.sync (HMMA) on sm_103.
// Round 9: single-term A_h * B_h (both operands fp16-quantized; measured
// residual-drop error budget: each residual contributes ~2.1e-4 norm-relative,
// combined ~2.9e-4 << 1e-3 threshold). Halves the HMMA instruction count vs
// round 8 (tensor-pipe floor ~56us at rt=8cyc/HMMA/SMSP).
// Pipeline: one full barrier per stage, warp-pair named barriers for the A
// buffer, B cp.async double-buffer a stage ahead, A LDGs inside the k-loop.
// ============================================================================

#define NTH 256
#define C_IN 256
#define APW_TOTAL 32760
#define REG_STRIDE_N (4 * APW_TOTAL)
#define CLS_STRIDE_N (9 * APW_TOTAL)
#define CONF_BASE (16 * 4 * APW_TOTAL)

#define LDK 72                        // smem row stride in halves (144 B)
#define A_BYTES (128 * LDK * 2)       // 18432 B (hi only)
#define B_STAGE_B (80 * LDK * 2)      // 11520 B per B stage (hi only)
#define B_OFF A_BYTES
#define SMEM_TOTAL (A_BYTES + 2 * B_STAGE_B)   // 41472

// B pack: [head 2][stage 36][n 80][k 72] halves (stage = tap*4+kc), hi only
#define BPACK_TILE (80 * LDK)
#define BPACK_ELEMS (2 * 36 * BPACK_TILE)
__device__ __align__(16) __half g_bpack[BPACK_ELEMS];
__device__ float g_bias[2 * 80];

// ---------------------------------------------------------------------------
__device__ __forceinline__ uint32_t smem_u32(const void* p) {
    uint32_t a;
    asm("{ .reg .u64 t; cvta.to.shared.u64 t, %1; cvt.u32.u64 %0, t; }" : "=r"(a) : "l"(p));
    return a;
}
__device__ __forceinline__ void cp_async16(uint32_t dst, const void* src) {
    asm volatile("cp.async.cg.shared.global [%0], [%1], 16;" :: "r"(dst), "l"(src));
}
#define CP_COMMIT() asm volatile("cp.async.commit_group;" ::: "memory")
#define CP_WAIT0()  asm volatile("cp.async.wait_group 0;" ::: "memory")
#define PAIR_BAR(id) asm volatile("bar.sync %0, 64;" :: "r"(id) : "memory")

__device__ __forceinline__ void ldsm_x4(uint32_t& r0, uint32_t& r1, uint32_t& r2, uint32_t& r3,
                                        uint32_t addr) {
    asm volatile("ldmatrix.sync.aligned.m8n8.x4.shared.b16 {%0,%1,%2,%3}, [%4];"
                 : "=r"(r0), "=r"(r1), "=r"(r2), "=r"(r3) : "r"(addr));
}
__device__ __forceinline__ void ldsm_x2(uint32_t& r0, uint32_t& r1, uint32_t addr) {
    asm volatile("ldmatrix.sync.aligned.m8n8.x2.shared.b16 {%0,%1}, [%2];"
                 : "=r"(r0), "=r"(r1) : "r"(addr));
}
__device__ __forceinline__ void mma_16816(float* d, const uint32_t* a, uint32_t b0, uint32_t b1) {
    asm volatile("mma.sync.aligned.m16n8k16.row.col.f32.f16.f16.f32 "
                 "{%0,%1,%2,%3}, {%4,%5,%6,%7}, {%8,%9}, {%0,%1,%2,%3};"
                 : "+f"(d[0]), "+f"(d[1]), "+f"(d[2]), "+f"(d[3])
                 : "r"(a[0]), "r"(a[1]), "r"(a[2]), "r"(a[3]), "r"(b0), "r"(b1));
}

// ---------------------------------------------------------------------------
// Repack: weights -> fp16, [head][stage][n80][k72]; biases.
// ---------------------------------------------------------------------------
__global__ void repack_kernel(const float* __restrict__ wr1, const float* __restrict__ br1,
                              const float* __restrict__ wc1, const float* __restrict__ bc1,
                              const float* __restrict__ wr2, const float* __restrict__ br2,
                              const float* __restrict__ wc2, const float* __restrict__ bc2)
{
    int idx = blockIdx.x * blockDim.x + threadIdx.x;
    if (idx < BPACK_ELEMS) {
        int k     = idx % LDK;
        int n     = (idx / LDK) % 80;
        int stage = (idx / (LDK * 80)) % 36;
        int head  = idx / (LDK * 80 * 36);
        int kc  = stage & 3;
        int tap = stage >> 2;
        float w = 0.0f;
        if (k < 64) {
            int ci = kc * 64 + k;
            const float* wr = head ? wr2 : wr1;
            const float* wc = head ? wc2 : wc1;
            if (n < 24)      w = wr[(n * C_IN + ci) * 9 + tap];
            else if (n < 78) w = wc[((n - 24) * C_IN + ci) * 9 + tap];
        }
        g_bpack[idx] = __float2half_rn(w);
    }
    if (idx < 160) {
        int head = idx / 80, o = idx % 80;
        const float* br = head ? br2 : br1;
        const float* bc = head ? bc2 : bc1;
        float v = 0.0f;
        if (o < 24)      v = br[o];
        else if (o < 78) v = bc[o - 24];
        g_bias[idx] = v;
    }
}

// ---------------------------------------------------------------------------
__device__ __forceinline__ void store_one(float* __restrict__ out, int o, float val,
                                          int n_img, int off_l, int HW, int p, int head)
{
    float bias = g_bias[head * 80 + o];
    int idx;
    if (o < 24) {
        int c = o / 6, a = o % 6;
        idx = n_img * REG_STRIDE_N + c * APW_TOTAL + off_l + a * HW + p;
    } else {
        int oc = o - 24;
        int c = oc / 6, a = oc % 6;
        idx = CONF_BASE + n_img * CLS_STRIDE_N + c * APW_TOTAL + off_l + a * HW + p;
    }
    out[idx] = val + bias;
}

// ---------------------------------------------------------------------------
// Main kernel: 683 CTAs x 256 threads.
// CTAs per level (128 rows over flattened img*HW): {512,128,32,8,2,1}.
// ---------------------------------------------------------------------------
__global__ __launch_bounds__(NTH, 2) void head_kernel(
    const float* __restrict__ f0, const float* __restrict__ f1,
    const float* __restrict__ f2, const float* __restrict__ f3,
    const float* __restrict__ f4, const float* __restrict__ f5,
    float* __restrict__ out)
{
    extern __shared__ char smem_c[];
    const uint32_t sm = smem_u32(smem_c);
    const int t = threadIdx.x;
    const int wid = t >> 5;
    const int lane = t & 31;
    const int pair_id = (wid & 3) + 1;     // named barrier per warp pair {w, w+4}

    // ---- block -> (level, rem) over flattened img*HW rows ----
    int b = blockIdx.x;
    int level, rem;
    if      (b < 512) { level = 0; rem = b;       }
    else if (b < 640) { level = 1; rem = b - 512; }
    else if (b < 672) { level = 2; rem = b - 640; }
    else if (b < 680) { level = 3; rem = b - 672; }
    else if (b < 682) { level = 4; rem = b - 680; }
    else              { level = 5; rem = b - 682; }
    const int logW = 6 - level;
    const int W  = 1 << logW;
    const int HW = 1 << (2 * logW);
    const int head = (level < 2) ? 0 : 1;
    const float* X = (level == 0) ? f0 : (level == 1) ? f1 : (level == 2) ? f2
                   : (level == 3) ? f3 : (level == 4) ? f4 : f5;
    const int lvl_off[6] = {0, 24576, 30720, 32256, 32640, 32736};
    const int off_l = lvl_off[level];
    const int u0 = rem << 7;

    // ---- A-build mapping: thread -> (row m, half of the 64-ch chunk) ----
    const int m  = t & 127;
    const int kh = t >> 7;
    const int u  = u0 + m;
    const bool rv = (u < (HW << 4));
    const int img = rv ? (u >> (2 * logW)) : 0;
    const int pos = u & (HW - 1);
    const int h0 = pos >> logW;
    const int w0 = pos & (W - 1);
    const float* Xn = X + (long)img * C_IN * HW;

    // ---- MMA mapping: warp grid 4(M) x 2(N), warp tile m32 x n40 ----
    const int wm = (wid & 3) << 5;
    const int wn = (wid >> 2) * 40;
    const int arow = lane & 15, acol = lane >> 4;
    const int brow4 = (lane & 7) + ((lane >> 4) << 3), bcol4 = (lane >> 3) & 1;
    const int brow2 = (lane & 7), bcol2 = (lane >> 3) & 1;

    float acc[2][5][4];
#pragma unroll
    for (int i = 0; i < 2; i++)
#pragma unroll
        for (int j = 0; j < 5; j++)
#pragma unroll
            for (int r = 0; r < 4; r++) acc[i][j][r] = 0.0f;

    const char* bpack_base = (const char*)(g_bpack) +
        (size_t)(head * 36) * BPACK_TILE * sizeof(__half);

    float xs[32];

    // ---- prologue: B(0) cp.async; A(0) LDG+convert+STS; sync ----
    {
        uint32_t dst = sm + B_OFF;
#pragma unroll
        for (int i = 0; i < 3; i++) {
            int idx = t + i * NTH;
            if (idx < 720) cp_async16(dst + idx * 16, bpack_base + idx * 16);
        }
        CP_COMMIT();

        const int hh = h0 - 1, ww = w0 - 1;   // tap 0: dy=-1, dx=-1; kc 0
        const bool v = rv & ((unsigned)hh < (unsigned)W) & ((unsigned)ww < (unsigned)W);
        const float* aptr = Xn + (v ? (hh * W + ww) : 0) + (kh * 32) * (long)HW;
#pragma unroll
        for (int j = 0; j < 32; j++) xs[j] = v ? __ldg(aptr + j * HW) : 0.0f;

        uint32_t hw_[16];
#pragma unroll
        for (int j = 0; j < 16; j++) {
            __half2 h2 = __floats2half2_rn(xs[2 * j], xs[2 * j + 1]);
            hw_[j] = *reinterpret_cast<uint32_t*>(&h2);
        }
        char* arow_p = smem_c + m * (LDK * 2) + kh * 64;
        *reinterpret_cast<uint4*>(arow_p)      = make_uint4(hw_[0], hw_[1], hw_[2], hw_[3]);
        *reinterpret_cast<uint4*>(arow_p + 16) = make_uint4(hw_[4], hw_[5], hw_[6], hw_[7]);
        *reinterpret_cast<uint4*>(arow_p + 32) = make_uint4(hw_[8], hw_[9], hw_[10], hw_[11]);
        *reinterpret_cast<uint4*>(arow_p + 48) = make_uint4(hw_[12], hw_[13], hw_[14], hw_[15]);

        CP_WAIT0();
        __syncthreads();
    }

    for (int s = 0; s < 36; ++s) {
        const bool more = (s + 1 < 36);

        // ---- issue B(s+1) into buf[(s+1)&1] (freed by last stage's sync) ----
        if (more) {
            const char* src = bpack_base + (size_t)(s + 1) * BPACK_TILE * sizeof(__half);
            uint32_t dst = sm + B_OFF + (((s + 1) & 1) ? B_STAGE_B : 0);
#pragma unroll
            for (int i = 0; i < 3; i++) {
                int idx = t + i * NTH;
                if (idx < 720) cp_async16(dst + idx * 16, src + idx * 16);
            }
            CP_COMMIT();
        }

        // ---- A(s+1) gmem address ----
        bool vN = false;
        const float* aptrN = Xn;
        if (more) {
            const int sn = s + 1;
            const int tap = sn >> 2;
            const int dy = tap / 3 - 1, dx = tap % 3 - 1;
            const int hh = h0 + dy, ww = w0 + dx;
            vN = rv & ((unsigned)hh < (unsigned)W) & ((unsigned)ww < (unsigned)W);
            aptrN = Xn + (vN ? (hh * W + ww) : 0) + ((sn & 3) * 64 + kh * 32) * (long)HW;
        }

        // ---- MMA(s): 4 k16 steps of Ah*Bh; prefetch LDGs at ks 0,1 ----
        const uint32_t bbuf = sm + B_OFF + ((s & 1) ? B_STAGE_B : 0);
#pragma unroll
        for (int ks = 0; ks < 4; ks++) {
            const int kb = ks * 32;

            if (ks == 0 && more) {
#pragma unroll
                for (int j = 0; j < 16; j++) xs[j] = vN ? __ldg(aptrN + j * HW) : 0.0f;
            }
            if (ks == 1 && more) {
#pragma unroll
                for (int j = 16; j < 32; j++) xs[j] = vN ? __ldg(aptrN + j * HW) : 0.0f;
            }

            uint32_t ah[2][4];
#pragma unroll
            for (int mi = 0; mi < 2; mi++) {
                uint32_t ad = sm + (wm + mi * 16 + arow) * (LDK * 2) + kb + acol * 16;
                ldsm_x4(ah[mi][0], ah[mi][1], ah[mi][2], ah[mi][3], ad);
            }

            uint32_t bh[10];
            {
                uint32_t b0 = bbuf + kb;
                ldsm_x4(bh[0], bh[1], bh[2], bh[3], b0 + (wn + brow4) * (LDK * 2) + bcol4 * 16);
                ldsm_x4(bh[4], bh[5], bh[6], bh[7], b0 + (wn + 16 + brow4) * (LDK * 2) + bcol4 * 16);
                ldsm_x2(bh[8], bh[9],             b0 + (wn + 32 + brow2) * (LDK * 2) + bcol2 * 16);
            }
#pragma unroll
            for (int mi = 0; mi < 2; mi++)
#pragma unroll
                for (int nj = 0; nj < 5; nj++)
                    mma_16816(acc[mi][nj], ah[mi], bh[2 * nj], bh[2 * nj + 1]);
        }

        // ---- convert A(s+1), pair-barrier, STS into the single A buffer ----
        if (more) {
            uint32_t hw_[16];
#pragma unroll
            for (int j = 0; j < 16; j++) {
                __half2 h2 = __floats2half2_rn(xs[2 * j], xs[2 * j + 1]);
                hw_[j] = *reinterpret_cast<uint32_t*>(&h2);
            }

            PAIR_BAR(pair_id);   // partner warp done reading A rows of this pair

            char* arow_p = smem_c + m * (LDK * 2) + kh * 64;
            *reinterpret_cast<uint4*>(arow_p)      = make_uint4(hw_[0], hw_[1], hw_[2], hw_[3]);
            *reinterpret_cast<uint4*>(arow_p + 16) = make_uint4(hw_[4], hw_[5], hw_[6], hw_[7]);
            *reinterpret_cast<uint4*>(arow_p + 32) = make_uint4(hw_[8], hw_[9], hw_[10], hw_[11]);
            *reinterpret_cast<uint4*>(arow_p + 48) = make_uint4(hw_[12], hw_[13], hw_[14], hw_[15]);
        }

        CP_WAIT0();        // B(s+1) landed (issued a full stage ago)
        __syncthreads();   // B buffer handoff + A visibility across pairs
    }

    // ---- epilogue: bias + scatter ----
#pragma unroll
    for (int mi = 0; mi < 2; mi++) {
        const int ur0 = u0 + wm + mi * 16 + (lane >> 2);
#pragma unroll
        for (int half = 0; half < 2; half++) {
            const int ur = ur0 + half * 8;
            if (ur >= (HW << 4)) continue;
            const int img_e = ur >> (2 * logW);
            const int p_e   = ur & (HW - 1);
#pragma unroll
            for (int nj = 0; nj < 5; nj++) {
                const int o0 = wn + nj * 8 + (lane & 3) * 2;
                const float v0 = acc[mi][nj][half * 2];
                const float v1 = acc[mi][nj][half * 2 + 1];
                if (o0 < 78)     store_one(out, o0,     v0, img_e, off_l, HW, p_e, head);
                if (o0 + 1 < 78) store_one(out, o0 + 1, v1, img_e, off_l, HW, p_e, head);
            }
        }
    }
}

// ---------------------------------------------------------------------------
extern "C" void kernel_launch(void* const* d_in, const int* in_sizes, int n_in,
                              void* d_out, int out_size)
{
    cudaFuncSetAttribute(head_kernel, cudaFuncAttributeMaxDynamicSharedMemorySize, SMEM_TOTAL);

    repack_kernel<<<(BPACK_ELEMS + NTH - 1) / NTH, NTH>>>(
        (const float*)d_in[6],  (const float*)d_in[7],
        (const float*)d_in[8],  (const float*)d_in[9],
        (const float*)d_in[10], (const float*)d_in[11],
        (const float*)d_in[12], (const float*)d_in[13]);

    head_kernel<<<683, NTH, SMEM_TOTAL>>>(
        (const float*)d_in[0], (const float*)d_in[1], (const float*)d_in[2],
        (const float*)d_in[3], (const float*)d_in[4], (const float*)d_in[5],
        (float*)d_out);
}